// round 16
// baseline (speedup 1.0000x reference)
#include <cuda_runtime.h>
#include <cuda_bf16.h>
#include <math.h>
#include <cstdint>

// Problem constants
#define BSZ 4
#define TLEN 2048
#define CDIM 1024
#define NH 16
#define HD 64
#define LCH 64
#define NC (TLEN / LCH)
#define BH (BSZ * NH)
#define MROWS (BSZ * TLEN)
#define STATE (HD * HD + HD)
#define EPSV 1e-6f

// ---------------------------------------------------------------------------
// Scratch (device globals; no allocations allowed)
// ---------------------------------------------------------------------------
__device__ float g_qkv[(size_t)MROWS * 3 * CDIM];
__device__ float g_y[(size_t)MROWS * CDIM];
__device__ float g_kvloc[(size_t)BH * NC * STATE];
__device__ float g_kvpre[(size_t)BH * NC * STATE];

__device__ __nv_bfloat16 g_xhi[(size_t)MROWS * CDIM];
__device__ __nv_bfloat16 g_xlo[(size_t)MROWS * CDIM];
__device__ __nv_bfloat16 g_yhi[(size_t)MROWS * CDIM];
__device__ __nv_bfloat16 g_ylo[(size_t)MROWS * CDIM];
__device__ __nv_bfloat16 g_wahi[(size_t)3 * CDIM * CDIM];  // [3072,1024] (N,K)
__device__ __nv_bfloat16 g_walo[(size_t)3 * CDIM * CDIM];
__device__ __nv_bfloat16 g_wphi[(size_t)CDIM * CDIM];      // [1024,1024] (N,K)
__device__ __nv_bfloat16 g_wplo[(size_t)CDIM * CDIM];

__device__ __forceinline__ float phi(float x) { return x > 0.f ? x + 1.f : expf(x); }

__device__ __forceinline__ uint32_t smem_u32(const void* p) {
    uint32_t a;
    asm("{ .reg .u64 t; cvta.to.shared.u64 t, %1; cvt.u32.u64 %0, t; }" : "=r"(a) : "l"(p));
    return a;
}

// ---------------------------------------------------------------------------
// Split converters
// ---------------------------------------------------------------------------
__global__ __launch_bounds__(256) void split_rm(
    const float* __restrict__ s, __nv_bfloat16* __restrict__ hi,
    __nv_bfloat16* __restrict__ lo, int n)
{
    int i = (blockIdx.x * 256 + threadIdx.x) * 4;
    if (i >= n) return;
    float4 v = *(const float4*)(s + i);
    __nv_bfloat16 h0 = __float2bfloat16(v.x), h1 = __float2bfloat16(v.y);
    __nv_bfloat16 h2 = __float2bfloat16(v.z), h3 = __float2bfloat16(v.w);
    __nv_bfloat162 hA; hA.x = h0; hA.y = h1;
    __nv_bfloat162 hB; hB.x = h2; hB.y = h3;
    __nv_bfloat162 lA, lB;
    lA.x = __float2bfloat16(v.x - __bfloat162float(h0));
    lA.y = __float2bfloat16(v.y - __bfloat162float(h1));
    lB.x = __float2bfloat16(v.z - __bfloat162float(h2));
    lB.y = __float2bfloat16(v.w - __bfloat162float(h3));
    *(__nv_bfloat162*)(hi + i) = hA; *(__nv_bfloat162*)(hi + i + 2) = hB;
    *(__nv_bfloat162*)(lo + i) = lA; *(__nv_bfloat162*)(lo + i + 2) = lB;
}

// W [K,N] row-major -> W^T hi/lo [N,K] row-major, split to bf16
__global__ __launch_bounds__(256) void split_tr(
    const float* __restrict__ W, __nv_bfloat16* __restrict__ hiT,
    __nv_bfloat16* __restrict__ loT, int Kd, int Nd)
{
    __shared__ float t[32][33];
    const int x0 = blockIdx.x * 32;  // N
    const int y0 = blockIdx.y * 32;  // K
    const int tx = threadIdx.x & 31, ty = threadIdx.x >> 5;  // (32,8)
    #pragma unroll
    for (int j = 0; j < 4; j++)
        t[ty + j * 8][tx] = W[(size_t)(y0 + ty + j * 8) * Nd + x0 + tx];
    __syncthreads();
    #pragma unroll
    for (int j = 0; j < 4; j++) {
        const int n = x0 + ty + j * 8, k = y0 + tx;
        float v = t[tx][ty + j * 8];
        __nv_bfloat16 h = __float2bfloat16(v);
        hiT[(size_t)n * Kd + k] = h;
        loT[(size_t)n * Kd + k] = __float2bfloat16(v - __bfloat162float(h));
    }
}

// ---------------------------------------------------------------------------
// HMMA (mma.sync) bf16 3-way-split GEMM:
//   C[M,N] = (Ahi+Alo)[M,K] @ ((Bhi+Blo)[N,K])^T + bias   (fp32 out)
// CTA tile 128x128, 16 warps (4x4), warp tile 32x32.
// SMEM row = 128B: [k0..31 hi | k0..31 lo], swizzle b ^= (row&7)<<4.
// 4-stage cp.async pipeline; k processed in k16-slice units (2 per kt)
// with CROSS-ITERATION register double buffering: LDSMs for slice u+1
// are issued before the MMAs of slice u, so every MMA is ready at issue
// and LDSM crossbar time hides under tensor time.
// ---------------------------------------------------------------------------
#define STG_A  16384
#define STG_SZ 32768
#define GEMM_SMEM (4 * STG_SZ)

__device__ __forceinline__ void ldsm4(uint32_t tb, int row0, int bbyte, int lane,
                                      uint32_t* r) {
    const int g = lane >> 3;
    const int row = row0 + ((g & 1) << 3) + (lane & 7);
    const int b = bbyte + ((g >> 1) << 4);
    const uint32_t a = tb + row * 128 + (b ^ ((row & 7) << 4));
    asm volatile("ldmatrix.sync.aligned.m8n8.x4.shared.b16 {%0,%1,%2,%3}, [%4];"
                 : "=r"(r[0]), "=r"(r[1]), "=r"(r[2]), "=r"(r[3]) : "r"(a));
}

__device__ __forceinline__ void mma16816(float* d, const uint32_t* a,
                                         uint32_t b0, uint32_t b1) {
    asm volatile(
        "mma.sync.aligned.m16n8k16.row.col.f32.bf16.bf16.f32 "
        "{%0,%1,%2,%3}, {%4,%5,%6,%7}, {%8,%9}, {%0,%1,%2,%3};"
        : "+f"(d[0]), "+f"(d[1]), "+f"(d[2]), "+f"(d[3])
        : "r"(a[0]), "r"(a[1]), "r"(a[2]), "r"(a[3]), "r"(b0), "r"(b1));
}

// 8 MMAs: one 32x32 warp tile update from a[2][4] x b[2][4] fragments
__device__ __forceinline__ void mma_block(float acc[2][4][4],
    const uint32_t a[2][4], const uint32_t b[2][4]) {
    #pragma unroll
    for (int ma = 0; ma < 2; ma++)
        #pragma unroll
        for (int na = 0; na < 4; na++)
            mma16816(acc[ma][na], a[ma], b[na >> 1][na & 1], b[na >> 1][(na & 1) + 2]);
}

__global__ __launch_bounds__(512, 1) void gemm_bf16x3(
    const __nv_bfloat16* __restrict__ Ahi, const __nv_bfloat16* __restrict__ Alo,
    const __nv_bfloat16* __restrict__ Bhi, const __nv_bfloat16* __restrict__ Blo,
    const float* __restrict__ bias, float* __restrict__ C, int N, int K)
{
    extern __shared__ char smc[];
    const uint32_t sb = smem_u32(smc);
    const int tid = threadIdx.x;
    const int lane = tid & 31, wid = tid >> 5;
    const int wm = wid >> 2, wn = wid & 3;          // 4x4 warp grid
    const int arow0 = blockIdx.y * 128, brow0 = blockIdx.x * 128;
    const int NKT = K >> 5;

    // cp.async stage loader: 2048 16B chunks/stage, 4 per thread
    auto issue = [&](int s, int kt) {
        const int kb = kt * 32;
        const uint32_t stg = sb + s * STG_SZ;
        #pragma unroll
        for (int t = 0; t < 4; t++) {
            const int idx = t * 512 + tid;
            const int isB = idx >> 10;
            const int r = (idx & 1023) >> 3;
            const int c = idx & 7;
            const int sp = c >> 2, cc = c & 3;
            const __nv_bfloat16* g = isB
                ? (sp ? Blo : Bhi) + (size_t)(brow0 + r) * K + kb + cc * 8
                : (sp ? Alo : Ahi) + (size_t)(arow0 + r) * K + kb + cc * 8;
            const uint32_t d = stg + isB * STG_A + r * 128
                             + ((sp * 64 + cc * 16) ^ ((r & 7) << 4));
            const unsigned long long gg = (unsigned long long)__cvta_generic_to_global(g);
            asm volatile("cp.async.cg.shared.global [%0], [%1], 16;" :: "r"(d), "l"(gg));
        }
    };

    float acc[2][4][4] = {};
    // fragment slots: [slot][hi=0/lo=1][frag-idx][4 regs]
    uint32_t fa[2][2][2][4];
    uint32_t fb[2][2][2][4];

    // load fragments of k16-slice u into register slot
    auto load_slot = [&](int slot, int u) {
        const uint32_t stg = sb + ((u >> 1) & 3) * STG_SZ;
        const uint32_t sA = stg, sB = stg + STG_A;
        const int off = (u & 1) * 32;
        ldsm4(sA, wm * 32,      off,      lane, fa[slot][0][0]);
        ldsm4(sA, wm * 32 + 16, off,      lane, fa[slot][0][1]);
        ldsm4(sB, wn * 32,      off,      lane, fb[slot][0][0]);
        ldsm4(sB, wn * 32 + 16, off,      lane, fb[slot][0][1]);
        ldsm4(sA, wm * 32,      64 + off, lane, fa[slot][1][0]);
        ldsm4(sA, wm * 32 + 16, 64 + off, lane, fa[slot][1][1]);
        ldsm4(sB, wn * 32,      64 + off, lane, fb[slot][1][0]);
        ldsm4(sB, wn * 32 + 16, 64 + off, lane, fb[slot][1][1]);
    };

    // prologue: 3 stages in flight; wait until stages 0 AND 1 resident
    #pragma unroll
    for (int s = 0; s < 3; s++) {
        issue(s, s);
        asm volatile("cp.async.commit_group;" ::: "memory");
    }
    asm volatile("cp.async.wait_group 1;" ::: "memory");
    __syncthreads();
    load_slot(0, 0);                 // only blocking LDSM burst in the kernel

    const int NU = 2 * NKT;          // k16-slice units
    int cur = 0;
    for (int u = 0; u < NU; u++) {
        const int kt = u >> 1;
        if ((u & 1) == 0) {
            // one group per kt; buffer (kt+3)&3 == (kt-1)&3 whose fragment
            // reads all finished before the end-of-(kt-1) barrier.
            if (kt + 3 < NKT) issue((kt + 3) & 3, kt + 3);
            asm volatile("cp.async.commit_group;" ::: "memory");
        }
        // prefetch fragments for slice u+1 (stage visible: end-of-kt wait
        // guarantees stages <= kt+2; preheat guarantees stages 0,1)
        if (u + 1 < NU) load_slot(cur ^ 1, u + 1);

        // MMAs of slice u from registers filled LAST iteration: ready at issue
        mma_block(acc, fa[cur][0], fb[cur][0]);   // hi*hi
        mma_block(acc, fa[cur][0], fb[cur][1]);   // hi*lo
        mma_block(acc, fa[cur][1], fb[cur][0]);   // lo*hi

        if (u & 1) {                 // end of kt
            asm volatile("cp.async.wait_group 1;" ::: "memory");
            __syncthreads();
        }
        cur ^= 1;
    }

    // epilogue: bias + store fp32
    const int r = lane >> 2, c2 = (lane & 3) * 2;
    #pragma unroll
    for (int ma = 0; ma < 2; ma++) {
        const int grow0 = arow0 + wm * 32 + ma * 16 + r;
        #pragma unroll
        for (int na = 0; na < 4; na++) {
            const int gc = brow0 + wn * 32 + na * 8 + c2;
            const float2 bv = *(const float2*)(bias + gc);
            float2 w0, w1;
            w0.x = acc[ma][na][0] + bv.x; w0.y = acc[ma][na][1] + bv.y;
            w1.x = acc[ma][na][2] + bv.x; w1.y = acc[ma][na][3] + bv.y;
            *(float2*)(C + (size_t)grow0 * N + gc) = w0;
            *(float2*)(C + (size_t)(grow0 + 8) * N + gc) = w1;
        }
    }
}

// ---------------------------------------------------------------------------
// Attention chain (unchanged, passed R3/R8/R10/R13/R14)
// ---------------------------------------------------------------------------
__global__ __launch_bounds__(256) void chunk_stats() {
    __shared__ float ks[LCH][HD];
    __shared__ float vs[LCH][HD];
    const int blk = blockIdx.x;
    const int bh = blk / NC, c = blk % NC;
    const int b = bh / NH, h = bh % NH;
    const int tid = threadIdx.x;

    const float* kb = g_qkv + (size_t)(b * TLEN + c * LCH) * 3 * CDIM + CDIM + h * HD;
    const float* vb = kb + CDIM;
    for (int i = tid; i < LCH * (HD / 4); i += 256) {
        const int r = i / (HD / 4), c4 = (i % (HD / 4)) * 4;
        float4 kk = *(const float4*)(kb + (size_t)r * 3 * CDIM + c4);
        kk.x = phi(kk.x); kk.y = phi(kk.y); kk.z = phi(kk.z); kk.w = phi(kk.w);
        *(float4*)&ks[r][c4] = kk;
        *(float4*)&vs[r][c4] = *(const float4*)(vb + (size_t)r * 3 * CDIM + c4);
    }
    __syncthreads();

    const int tx = tid & 15, ty = tid >> 4;
    const int i0 = ty * 4, j0 = tx * 4;
    float acc[4][4] = {};
    for (int t = 0; t < LCH; t++) {
        float4 a = *(const float4*)&ks[t][i0];
        float4 bb = *(const float4*)&vs[t][j0];
        float av[4] = {a.x, a.y, a.z, a.w};
        float bv[4] = {bb.x, bb.y, bb.z, bb.w};
        #pragma unroll
        for (int ii = 0; ii < 4; ii++)
            #pragma unroll
            for (int jj = 0; jj < 4; jj++)
                acc[ii][jj] += av[ii] * bv[jj];
    }
    float* outp = g_kvloc + (size_t)blk * STATE;
    #pragma unroll
    for (int ii = 0; ii < 4; ii++) {
        float4 w = {acc[ii][0], acc[ii][1], acc[ii][2], acc[ii][3]};
        *(float4*)&outp[(i0 + ii) * HD + j0] = w;
    }
    if (tid < HD) {
        float s = 0.f;
        for (int t = 0; t < LCH; t++) s += ks[t][tid];
        outp[HD * HD + tid] = s;
    }
}

__global__ __launch_bounds__(256) void chunk_scan() {
    const int bh = blockIdx.x, tid = threadIdx.x;
    float st[17];
    #pragma unroll
    for (int k = 0; k < 17; k++) st[k] = 0.f;
    for (int c = 0; c < NC; c++) {
        const size_t base = ((size_t)bh * NC + c) * STATE;
        #pragma unroll
        for (int k = 0; k < 17; k++) {
            const int e = tid + k * 256;
            if (e < STATE) {
                g_kvpre[base + e] = st[k];
                st[k] += g_kvloc[base + e];
            }
        }
    }
}

__global__ __launch_bounds__(256) void attn_out() {
    extern __shared__ float smf[];
    float* Qt  = smf;
    float* Kt  = Qt + 64 * 68;
    float* Vs  = Kt + 64 * 68;
    float* St  = Vs + 64 * 68;
    float* KVp = St + 64 * 68;
    float* ksp = KVp + 64 * 68;
    float* den = ksp + 64;

    const int blk = blockIdx.x;
    const int bh = blk / NC, c = blk % NC;
    const int b = bh / NH, h = bh % NH;
    const int tid = threadIdx.x;

    const float* qb = g_qkv + (size_t)(b * TLEN + c * LCH) * 3 * CDIM + h * HD;
    const float* kb = qb + CDIM;
    const float* vb = qb + 2 * CDIM;

    for (int i = tid; i < LCH * (HD / 4); i += 256) {
        const int r = i / (HD / 4), c4 = (i % (HD / 4)) * 4;
        float4 q4 = *(const float4*)(qb + (size_t)r * 3 * CDIM + c4);
        q4.x = phi(q4.x); q4.y = phi(q4.y); q4.z = phi(q4.z); q4.w = phi(q4.w);
        Qt[(c4 + 0) * 68 + r] = q4.x; Qt[(c4 + 1) * 68 + r] = q4.y;
        Qt[(c4 + 2) * 68 + r] = q4.z; Qt[(c4 + 3) * 68 + r] = q4.w;
        float4 k4 = *(const float4*)(kb + (size_t)r * 3 * CDIM + c4);
        k4.x = phi(k4.x); k4.y = phi(k4.y); k4.z = phi(k4.z); k4.w = phi(k4.w);
        Kt[(c4 + 0) * 68 + r] = k4.x; Kt[(c4 + 1) * 68 + r] = k4.y;
        Kt[(c4 + 2) * 68 + r] = k4.z; Kt[(c4 + 3) * 68 + r] = k4.w;
        *(float4*)&Vs[r * 68 + c4] = *(const float4*)(vb + (size_t)r * 3 * CDIM + c4);
    }
    const float* pre = g_kvpre + (size_t)blk * STATE;
    for (int i = tid; i < HD * HD / 4; i += 256) {
        const int r = (i * 4) / HD, c4 = (i * 4) % HD;
        *(float4*)&KVp[r * 68 + c4] = *(const float4*)&pre[r * HD + c4];
    }
    if (tid < HD) ksp[tid] = pre[HD * HD + tid];
    __syncthreads();

    const int tx = tid & 15, ty = tid >> 4;
    const int t0 = ty * 4, s0 = tx * 4;

    float acc[4][4] = {};
    for (int k = 0; k < HD; k++) {
        float4 a = *(const float4*)&Qt[k * 68 + t0];
        float4 bb = *(const float4*)&Kt[k * 68 + s0];
        float av[4] = {a.x, a.y, a.z, a.w};
        float bv[4] = {bb.x, bb.y, bb.z, bb.w};
        #pragma unroll
        for (int ti = 0; ti < 4; ti++)
            #pragma unroll
            for (int si = 0; si < 4; si++)
                acc[ti][si] += av[ti] * bv[si];
    }
    #pragma unroll
    for (int si = 0; si < 4; si++) {
        const int s = s0 + si;
        float4 w;
        w.x = (s <= t0 + 0) ? acc[0][si] : 0.f;
        w.y = (s <= t0 + 1) ? acc[1][si] : 0.f;
        w.z = (s <= t0 + 2) ? acc[2][si] : 0.f;
        w.w = (s <= t0 + 3) ? acc[3][si] : 0.f;
        *(float4*)&St[s * 68 + t0] = w;
    }
    __syncthreads();

    if (tid < LCH) {
        const int t = tid;
        float dsum = EPSV;
        for (int s = 0; s < LCH; s++) dsum += St[s * 68 + t];
        for (int i = 0; i < HD; i++) dsum += Qt[i * 68 + t] * ksp[i];
        den[t] = dsum;
    }
    __syncthreads();

    const int j0 = s0;
    float o[4][4] = {};
    for (int s = 0; s < LCH; s++) {
        float4 a = *(const float4*)&St[s * 68 + t0];
        float4 bb = *(const float4*)&Vs[s * 68 + j0];
        float av[4] = {a.x, a.y, a.z, a.w};
        float bv[4] = {bb.x, bb.y, bb.z, bb.w};
        #pragma unroll
        for (int ti = 0; ti < 4; ti++)
            #pragma unroll
            for (int jj = 0; jj < 4; jj++)
                o[ti][jj] += av[ti] * bv[jj];
    }
    for (int i = 0; i < HD; i++) {
        float4 a = *(const float4*)&Qt[i * 68 + t0];
        float4 bb = *(const float4*)&KVp[i * 68 + j0];
        float av[4] = {a.x, a.y, a.z, a.w};
        float bv[4] = {bb.x, bb.y, bb.z, bb.w};
        #pragma unroll
        for (int ti = 0; ti < 4; ti++)
            #pragma unroll
            for (int jj = 0; jj < 4; jj++)
                o[ti][jj] += av[ti] * bv[jj];
    }

    float* yb = g_y + (size_t)(b * TLEN + c * LCH) * CDIM + h * HD;
    #pragma unroll
    for (int ti = 0; ti < 4; ti++) {
        const float invd = 1.f / den[t0 + ti];
        float4 w = {o[ti][0] * invd, o[ti][1] * invd, o[ti][2] * invd, o[ti][3] * invd};
        *(float4*)&yb[(size_t)(t0 + ti) * CDIM + j0] = w;
    }
}

// ---------------------------------------------------------------------------
extern "C" void kernel_launch(void* const* d_in, const int* in_sizes, int n_in,
                              void* d_out, int out_size)
{
    const float* x  = (const float*)d_in[0];
    const float* Wa = (const float*)d_in[1];
    const float* ba = (const float*)d_in[2];
    const float* Wp = (const float*)d_in[3];
    const float* bp = (const float*)d_in[4];
    float* out = (float*)d_out;

    float *qkv, *y;
    __nv_bfloat16 *xhi, *xlo, *yhi, *ylo, *wahi, *walo, *wphi, *wplo;
    cudaGetSymbolAddress((void**)&qkv, g_qkv);
    cudaGetSymbolAddress((void**)&y, g_y);
    cudaGetSymbolAddress((void**)&xhi, g_xhi);
    cudaGetSymbolAddress((void**)&xlo, g_xlo);
    cudaGetSymbolAddress((void**)&yhi, g_yhi);
    cudaGetSymbolAddress((void**)&ylo, g_ylo);
    cudaGetSymbolAddress((void**)&wahi, g_wahi);
    cudaGetSymbolAddress((void**)&walo, g_walo);
    cudaGetSymbolAddress((void**)&wphi, g_wphi);
    cudaGetSymbolAddress((void**)&wplo, g_wplo);

    cudaFuncSetAttribute(gemm_bf16x3, cudaFuncAttributeMaxDynamicSharedMemorySize, GEMM_SMEM);
    const size_t smem4 = (size_t)(5 * 64 * 68 + 128) * sizeof(float);
    cudaFuncSetAttribute(attn_out, cudaFuncAttributeMaxDynamicSharedMemorySize, (int)smem4);

    // 0) split inputs to bf16 hi/lo (weights also transposed to [N,K])
    {
        const int nx = MROWS * CDIM;
        split_rm<<<nx / 1024, 256>>>(x, xhi, xlo, nx);
        dim3 ga(3 * CDIM / 32, CDIM / 32);
        split_tr<<<ga, 256>>>(Wa, wahi, walo, CDIM, 3 * CDIM);
        dim3 gp(CDIM / 32, CDIM / 32);
        split_tr<<<gp, 256>>>(Wp, wphi, wplo, CDIM, CDIM);
    }
    // 1) qkv = x @ W_attn + b_attn  (HMMA, 3-way bf16 split)
    {
        dim3 grid(3 * CDIM / 128, MROWS / 128);
        gemm_bf16x3<<<grid, 512, GEMM_SMEM>>>(xhi, xlo, wahi, walo, ba, qkv, 3 * CDIM, CDIM);
    }
    // 2-4) chunked linear attention
    chunk_stats<<<BH * NC, 256>>>();
    chunk_scan<<<BH, 256>>>();
    attn_out<<<BH * NC, 256, smem4>>>();
    // 5) split y, then out = y @ W_proj + b_proj
    {
        const int ny = MROWS * CDIM;
        split_rm<<<ny / 1024, 256>>>(y, yhi, ylo, ny);
        dim3 grid(CDIM / 128, MROWS / 128);
        gemm_bf16x3<<<grid, 512, GEMM_SMEM>>>(yhi, ylo, wphi, wplo, bp, out, CDIM, CDIM);
    }
}

// round 17
// speedup vs baseline: 2.0743x; 2.0743x over previous
#include <cuda_runtime.h>
#include <cuda_bf16.h>
#include <math.h>
#include <cstdint>

// Problem constants
#define BSZ 4
#define TLEN 2048
#define CDIM 1024
#define NH 16
#define HD 64
#define LCH 64
#define NC (TLEN / LCH)
#define BH (BSZ * NH)
#define MROWS (BSZ * TLEN)
#define STATE (HD * HD + HD)
#define EPSV 1e-6f

// ---------------------------------------------------------------------------
// Scratch (device globals; no allocations allowed)
// ---------------------------------------------------------------------------
__device__ float g_qkv[(size_t)MROWS * 3 * CDIM];
__device__ float g_y[(size_t)MROWS * CDIM];
__device__ float g_kvloc[(size_t)BH * NC * STATE];
__device__ float g_kvpre[(size_t)BH * NC * STATE];

__device__ __nv_bfloat16 g_xhi[(size_t)MROWS * CDIM];
__device__ __nv_bfloat16 g_xlo[(size_t)MROWS * CDIM];
__device__ __nv_bfloat16 g_yhi[(size_t)MROWS * CDIM];
__device__ __nv_bfloat16 g_ylo[(size_t)MROWS * CDIM];
__device__ __nv_bfloat16 g_wahi[(size_t)3 * CDIM * CDIM];  // [3072,1024] (N,K)
__device__ __nv_bfloat16 g_walo[(size_t)3 * CDIM * CDIM];
__device__ __nv_bfloat16 g_wphi[(size_t)CDIM * CDIM];      // [1024,1024] (N,K)
__device__ __nv_bfloat16 g_wplo[(size_t)CDIM * CDIM];

__device__ __forceinline__ float phi(float x) { return x > 0.f ? x + 1.f : expf(x); }

__device__ __forceinline__ uint32_t smem_u32(const void* p) {
    uint32_t a;
    asm("{ .reg .u64 t; cvta.to.shared.u64 t, %1; cvt.u32.u64 %0, t; }" : "=r"(a) : "l"(p));
    return a;
}

// ---------------------------------------------------------------------------
// Split converters
// ---------------------------------------------------------------------------
__global__ __launch_bounds__(256) void split_rm(
    const float* __restrict__ s, __nv_bfloat16* __restrict__ hi,
    __nv_bfloat16* __restrict__ lo, int n)
{
    int i = (blockIdx.x * 256 + threadIdx.x) * 4;
    if (i >= n) return;
    float4 v = *(const float4*)(s + i);
    __nv_bfloat16 h0 = __float2bfloat16(v.x), h1 = __float2bfloat16(v.y);
    __nv_bfloat16 h2 = __float2bfloat16(v.z), h3 = __float2bfloat16(v.w);
    __nv_bfloat162 hA; hA.x = h0; hA.y = h1;
    __nv_bfloat162 hB; hB.x = h2; hB.y = h3;
    __nv_bfloat162 lA, lB;
    lA.x = __float2bfloat16(v.x - __bfloat162float(h0));
    lA.y = __float2bfloat16(v.y - __bfloat162float(h1));
    lB.x = __float2bfloat16(v.z - __bfloat162float(h2));
    lB.y = __float2bfloat16(v.w - __bfloat162float(h3));
    *(__nv_bfloat162*)(hi + i) = hA; *(__nv_bfloat162*)(hi + i + 2) = hB;
    *(__nv_bfloat162*)(lo + i) = lA; *(__nv_bfloat162*)(lo + i + 2) = lB;
}

// W [K,N] row-major -> W^T hi/lo [N,K] row-major, split to bf16
__global__ __launch_bounds__(256) void split_tr(
    const float* __restrict__ W, __nv_bfloat16* __restrict__ hiT,
    __nv_bfloat16* __restrict__ loT, int Kd, int Nd)
{
    __shared__ float t[32][33];
    const int x0 = blockIdx.x * 32;  // N
    const int y0 = blockIdx.y * 32;  // K
    const int tx = threadIdx.x & 31, ty = threadIdx.x >> 5;  // (32,8)
    #pragma unroll
    for (int j = 0; j < 4; j++)
        t[ty + j * 8][tx] = W[(size_t)(y0 + ty + j * 8) * Nd + x0 + tx];
    __syncthreads();
    #pragma unroll
    for (int j = 0; j < 4; j++) {
        const int n = x0 + ty + j * 8, k = y0 + tx;
        float v = t[tx][ty + j * 8];
        __nv_bfloat16 h = __float2bfloat16(v);
        hiT[(size_t)n * Kd + k] = h;
        loT[(size_t)n * Kd + k] = __float2bfloat16(v - __bfloat162float(h));
    }
}

// ---------------------------------------------------------------------------
// HMMA (mma.sync) bf16 3-way-split GEMM:
//   C[M,N] = (Ahi+Alo)[M,K] @ ((Bhi+Blo)[N,K])^T + bias   (fp32 out)
// CTA tile 128x128, 16 warps (4x4), warp tile 32x32.
// SMEM row = 128B: [k0..31 hi | k0..31 lo], swizzle b ^= (row&7)<<4.
// 4-stage cp.async pipeline; k in k16-slice units (2/kt), cross-iteration
// register double buffering with STATIC slot names (fa0/fb0 vs fa1/fb1) —
// no runtime-indexed register arrays (R16's local-memory trap).
// ---------------------------------------------------------------------------
#define STG_A  16384
#define STG_SZ 32768
#define GEMM_SMEM (4 * STG_SZ)

__device__ __forceinline__ void ldsm4(uint32_t tb, int row0, int bbyte, int lane,
                                      uint32_t* r) {
    const int g = lane >> 3;
    const int row = row0 + ((g & 1) << 3) + (lane & 7);
    const int b = bbyte + ((g >> 1) << 4);
    const uint32_t a = tb + row * 128 + (b ^ ((row & 7) << 4));
    asm volatile("ldmatrix.sync.aligned.m8n8.x4.shared.b16 {%0,%1,%2,%3}, [%4];"
                 : "=r"(r[0]), "=r"(r[1]), "=r"(r[2]), "=r"(r[3]) : "r"(a));
}

__device__ __forceinline__ void mma16816(float* d, const uint32_t* a,
                                         uint32_t b0, uint32_t b1) {
    asm volatile(
        "mma.sync.aligned.m16n8k16.row.col.f32.bf16.bf16.f32 "
        "{%0,%1,%2,%3}, {%4,%5,%6,%7}, {%8,%9}, {%0,%1,%2,%3};"
        : "+f"(d[0]), "+f"(d[1]), "+f"(d[2]), "+f"(d[3])
        : "r"(a[0]), "r"(a[1]), "r"(a[2]), "r"(a[3]), "r"(b0), "r"(b1));
}

// 8 MMAs: one 32x32 warp tile update from a[2][4] x b[2][4] fragments
__device__ __forceinline__ void mma_block(float acc[2][4][4],
    const uint32_t a[2][4], const uint32_t b[2][4]) {
    #pragma unroll
    for (int ma = 0; ma < 2; ma++)
        #pragma unroll
        for (int na = 0; na < 4; na++)
            mma16816(acc[ma][na], a[ma], b[na >> 1][na & 1], b[na >> 1][(na & 1) + 2]);
}

__global__ __launch_bounds__(512, 1) void gemm_bf16x3(
    const __nv_bfloat16* __restrict__ Ahi, const __nv_bfloat16* __restrict__ Alo,
    const __nv_bfloat16* __restrict__ Bhi, const __nv_bfloat16* __restrict__ Blo,
    const float* __restrict__ bias, float* __restrict__ C, int N, int K)
{
    extern __shared__ char smc[];
    const uint32_t sb = smem_u32(smc);
    const int tid = threadIdx.x;
    const int lane = tid & 31, wid = tid >> 5;
    const int wm = wid >> 2, wn = wid & 3;          // 4x4 warp grid
    const int arow0 = blockIdx.y * 128, brow0 = blockIdx.x * 128;
    const int NKT = K >> 5;

    // cp.async stage loader: 2048 16B chunks/stage, 4 per thread
    auto issue = [&](int s, int kt) {
        const int kb = kt * 32;
        const uint32_t stg = sb + s * STG_SZ;
        #pragma unroll
        for (int t = 0; t < 4; t++) {
            const int idx = t * 512 + tid;
            const int isB = idx >> 10;
            const int r = (idx & 1023) >> 3;
            const int c = idx & 7;
            const int sp = c >> 2, cc = c & 3;
            const __nv_bfloat16* g = isB
                ? (sp ? Blo : Bhi) + (size_t)(brow0 + r) * K + kb + cc * 8
                : (sp ? Alo : Ahi) + (size_t)(arow0 + r) * K + kb + cc * 8;
            const uint32_t d = stg + isB * STG_A + r * 128
                             + ((sp * 64 + cc * 16) ^ ((r & 7) << 4));
            const unsigned long long gg = (unsigned long long)__cvta_generic_to_global(g);
            asm volatile("cp.async.cg.shared.global [%0], [%1], 16;" :: "r"(d), "l"(gg));
        }
    };

    float acc[2][4][4] = {};
    // two STATIC fragment slots (no runtime indexing -> stays in registers)
    uint32_t fa0[2][2][4], fb0[2][2][4];   // [hi=0/lo=1][frag][4]
    uint32_t fa1[2][2][4], fb1[2][2][4];

    // load fragments of k16-slice u into slot 0 / slot 1 (static targets)
    auto loadA = [&](int u) {
        const uint32_t stg = sb + ((u >> 1) & 3) * STG_SZ;
        const uint32_t sA = stg, sB = stg + STG_A;
        const int off = (u & 1) * 32;
        ldsm4(sA, wm * 32,      off,      lane, fa0[0][0]);
        ldsm4(sA, wm * 32 + 16, off,      lane, fa0[0][1]);
        ldsm4(sB, wn * 32,      off,      lane, fb0[0][0]);
        ldsm4(sB, wn * 32 + 16, off,      lane, fb0[0][1]);
        ldsm4(sA, wm * 32,      64 + off, lane, fa0[1][0]);
        ldsm4(sA, wm * 32 + 16, 64 + off, lane, fa0[1][1]);
        ldsm4(sB, wn * 32,      64 + off, lane, fb0[1][0]);
        ldsm4(sB, wn * 32 + 16, 64 + off, lane, fb0[1][1]);
    };
    auto loadB = [&](int u) {
        const uint32_t stg = sb + ((u >> 1) & 3) * STG_SZ;
        const uint32_t sA = stg, sB = stg + STG_A;
        const int off = (u & 1) * 32;
        ldsm4(sA, wm * 32,      off,      lane, fa1[0][0]);
        ldsm4(sA, wm * 32 + 16, off,      lane, fa1[0][1]);
        ldsm4(sB, wn * 32,      off,      lane, fb1[0][0]);
        ldsm4(sB, wn * 32 + 16, off,      lane, fb1[0][1]);
        ldsm4(sA, wm * 32,      64 + off, lane, fa1[1][0]);
        ldsm4(sA, wm * 32 + 16, 64 + off, lane, fa1[1][1]);
        ldsm4(sB, wn * 32,      64 + off, lane, fb1[1][0]);
        ldsm4(sB, wn * 32 + 16, 64 + off, lane, fb1[1][1]);
    };

    // prologue: 3 stages in flight; stage 0 resident; slice 0 in slot A
    #pragma unroll
    for (int s = 0; s < 3; s++) {
        issue(s, s);
        asm volatile("cp.async.commit_group;" ::: "memory");
    }
    asm volatile("cp.async.wait_group 2;" ::: "memory");
    __syncthreads();
    loadA(0);                        // only blocking LDSM burst in the kernel

    for (int kt = 0; kt < NKT; kt++) {
        // overwrite buffer (kt+3)&3 == (kt-1)&3: stage kt-1 fragment reads
        // (loadB of iteration kt-1) finished before its mid-iteration barrier.
        if (kt + 3 < NKT) issue((kt + 3) & 3, kt + 3);
        asm volatile("cp.async.commit_group;" ::: "memory");  // may be empty

        loadB(2 * kt + 1);                    // stage kt, resident

        // slice 2kt from slot A (registers filled last iteration/prologue)
        mma_block(acc, fa0[0], fb0[0]);       // hi*hi
        mma_block(acc, fa0[0], fb0[1]);       // hi*lo
        mma_block(acc, fa0[1], fb0[0]);       // lo*hi

        if (kt + 1 < NKT) {
            // stage kt+1 resident: commits = 3 + (kt+1), wait 2 pending
            asm volatile("cp.async.wait_group 2;" ::: "memory");
            __syncthreads();
            loadA(2 * kt + 2);                // stage kt+1, overlaps MMAs below
        }

        // slice 2kt+1 from slot B
        mma_block(acc, fa1[0], fb1[0]);       // hi*hi
        mma_block(acc, fa1[0], fb1[1]);       // hi*lo
        mma_block(acc, fa1[1], fb1[0]);       // lo*hi
    }

    // epilogue: bias + store fp32
    const int r = lane >> 2, c2 = (lane & 3) * 2;
    #pragma unroll
    for (int ma = 0; ma < 2; ma++) {
        const int grow0 = arow0 + wm * 32 + ma * 16 + r;
        #pragma unroll
        for (int na = 0; na < 4; na++) {
            const int gc = brow0 + wn * 32 + na * 8 + c2;
            const float2 bv = *(const float2*)(bias + gc);
            float2 w0, w1;
            w0.x = acc[ma][na][0] + bv.x; w0.y = acc[ma][na][1] + bv.y;
            w1.x = acc[ma][na][2] + bv.x; w1.y = acc[ma][na][3] + bv.y;
            *(float2*)(C + (size_t)grow0 * N + gc) = w0;
            *(float2*)(C + (size_t)(grow0 + 8) * N + gc) = w1;
        }
    }
}

// ---------------------------------------------------------------------------
// Attention chain (unchanged, passed R3/R8/R10/R13/R14)
// ---------------------------------------------------------------------------
__global__ __launch_bounds__(256) void chunk_stats() {
    __shared__ float ks[LCH][HD];
    __shared__ float vs[LCH][HD];
    const int blk = blockIdx.x;
    const int bh = blk / NC, c = blk % NC;
    const int b = bh / NH, h = bh % NH;
    const int tid = threadIdx.x;

    const float* kb = g_qkv + (size_t)(b * TLEN + c * LCH) * 3 * CDIM + CDIM + h * HD;
    const float* vb = kb + CDIM;
    for (int i = tid; i < LCH * (HD / 4); i += 256) {
        const int r = i / (HD / 4), c4 = (i % (HD / 4)) * 4;
        float4 kk = *(const float4*)(kb + (size_t)r * 3 * CDIM + c4);
        kk.x = phi(kk.x); kk.y = phi(kk.y); kk.z = phi(kk.z); kk.w = phi(kk.w);
        *(float4*)&ks[r][c4] = kk;
        *(float4*)&vs[r][c4] = *(const float4*)(vb + (size_t)r * 3 * CDIM + c4);
    }
    __syncthreads();

    const int tx = tid & 15, ty = tid >> 4;
    const int i0 = ty * 4, j0 = tx * 4;
    float acc[4][4] = {};
    for (int t = 0; t < LCH; t++) {
        float4 a = *(const float4*)&ks[t][i0];
        float4 bb = *(const float4*)&vs[t][j0];
        float av[4] = {a.x, a.y, a.z, a.w};
        float bv[4] = {bb.x, bb.y, bb.z, bb.w};
        #pragma unroll
        for (int ii = 0; ii < 4; ii++)
            #pragma unroll
            for (int jj = 0; jj < 4; jj++)
                acc[ii][jj] += av[ii] * bv[jj];
    }
    float* outp = g_kvloc + (size_t)blk * STATE;
    #pragma unroll
    for (int ii = 0; ii < 4; ii++) {
        float4 w = {acc[ii][0], acc[ii][1], acc[ii][2], acc[ii][3]};
        *(float4*)&outp[(i0 + ii) * HD + j0] = w;
    }
    if (tid < HD) {
        float s = 0.f;
        for (int t = 0; t < LCH; t++) s += ks[t][tid];
        outp[HD * HD + tid] = s;
    }
}

__global__ __launch_bounds__(256) void chunk_scan() {
    const int bh = blockIdx.x, tid = threadIdx.x;
    float st[17];
    #pragma unroll
    for (int k = 0; k < 17; k++) st[k] = 0.f;
    for (int c = 0; c < NC; c++) {
        const size_t base = ((size_t)bh * NC + c) * STATE;
        #pragma unroll
        for (int k = 0; k < 17; k++) {
            const int e = tid + k * 256;
            if (e < STATE) {
                g_kvpre[base + e] = st[k];
                st[k] += g_kvloc[base + e];
            }
        }
    }
}

__global__ __launch_bounds__(256) void attn_out() {
    extern __shared__ float smf[];
    float* Qt  = smf;
    float* Kt  = Qt + 64 * 68;
    float* Vs  = Kt + 64 * 68;
    float* St  = Vs + 64 * 68;
    float* KVp = St + 64 * 68;
    float* ksp = KVp + 64 * 68;
    float* den = ksp + 64;

    const int blk = blockIdx.x;
    const int bh = blk / NC, c = blk % NC;
    const int b = bh / NH, h = bh % NH;
    const int tid = threadIdx.x;

    const float* qb = g_qkv + (size_t)(b * TLEN + c * LCH) * 3 * CDIM + h * HD;
    const float* kb = qb + CDIM;
    const float* vb = qb + 2 * CDIM;

    for (int i = tid; i < LCH * (HD / 4); i += 256) {
        const int r = i / (HD / 4), c4 = (i % (HD / 4)) * 4;
        float4 q4 = *(const float4*)(qb + (size_t)r * 3 * CDIM + c4);
        q4.x = phi(q4.x); q4.y = phi(q4.y); q4.z = phi(q4.z); q4.w = phi(q4.w);
        Qt[(c4 + 0) * 68 + r] = q4.x; Qt[(c4 + 1) * 68 + r] = q4.y;
        Qt[(c4 + 2) * 68 + r] = q4.z; Qt[(c4 + 3) * 68 + r] = q4.w;
        float4 k4 = *(const float4*)(kb + (size_t)r * 3 * CDIM + c4);
        k4.x = phi(k4.x); k4.y = phi(k4.y); k4.z = phi(k4.z); k4.w = phi(k4.w);
        Kt[(c4 + 0) * 68 + r] = k4.x; Kt[(c4 + 1) * 68 + r] = k4.y;
        Kt[(c4 + 2) * 68 + r] = k4.z; Kt[(c4 + 3) * 68 + r] = k4.w;
        *(float4*)&Vs[r * 68 + c4] = *(const float4*)(vb + (size_t)r * 3 * CDIM + c4);
    }
    const float* pre = g_kvpre + (size_t)blk * STATE;
    for (int i = tid; i < HD * HD / 4; i += 256) {
        const int r = (i * 4) / HD, c4 = (i * 4) % HD;
        *(float4*)&KVp[r * 68 + c4] = *(const float4*)&pre[r * HD + c4];
    }
    if (tid < HD) ksp[tid] = pre[HD * HD + tid];
    __syncthreads();

    const int tx = tid & 15, ty = tid >> 4;
    const int t0 = ty * 4, s0 = tx * 4;

    float acc[4][4] = {};
    for (int k = 0; k < HD; k++) {
        float4 a = *(const float4*)&Qt[k * 68 + t0];
        float4 bb = *(const float4*)&Kt[k * 68 + s0];
        float av[4] = {a.x, a.y, a.z, a.w};
        float bv[4] = {bb.x, bb.y, bb.z, bb.w};
        #pragma unroll
        for (int ti = 0; ti < 4; ti++)
            #pragma unroll
            for (int si = 0; si < 4; si++)
                acc[ti][si] += av[ti] * bv[si];
    }
    #pragma unroll
    for (int si = 0; si < 4; si++) {
        const int s = s0 + si;
        float4 w;
        w.x = (s <= t0 + 0) ? acc[0][si] : 0.f;
        w.y = (s <= t0 + 1) ? acc[1][si] : 0.f;
        w.z = (s <= t0 + 2) ? acc[2][si] : 0.f;
        w.w = (s <= t0 + 3) ? acc[3][si] : 0.f;
        *(float4*)&St[s * 68 + t0] = w;
    }
    __syncthreads();

    if (tid < LCH) {
        const int t = tid;
        float dsum = EPSV;
        for (int s = 0; s < LCH; s++) dsum += St[s * 68 + t];
        for (int i = 0; i < HD; i++) dsum += Qt[i * 68 + t] * ksp[i];
        den[t] = dsum;
    }
    __syncthreads();

    const int j0 = s0;
    float o[4][4] = {};
    for (int s = 0; s < LCH; s++) {
        float4 a = *(const float4*)&St[s * 68 + t0];
        float4 bb = *(const float4*)&Vs[s * 68 + j0];
        float av[4] = {a.x, a.y, a.z, a.w};
        float bv[4] = {bb.x, bb.y, bb.z, bb.w};
        #pragma unroll
        for (int ti = 0; ti < 4; ti++)
            #pragma unroll
            for (int jj = 0; jj < 4; jj++)
                o[ti][jj] += av[ti] * bv[jj];
    }
    for (int i = 0; i < HD; i++) {
        float4 a = *(const float4*)&Qt[i * 68 + t0];
        float4 bb = *(const float4*)&KVp[i * 68 + j0];
        float av[4] = {a.x, a.y, a.z, a.w};
        float bv[4] = {bb.x, bb.y, bb.z, bb.w};
        #pragma unroll
        for (int ti = 0; ti < 4; ti++)
            #pragma unroll
            for (int jj = 0; jj < 4; jj++)
                o[ti][jj] += av[ti] * bv[jj];
    }

    float* yb = g_y + (size_t)(b * TLEN + c * LCH) * CDIM + h * HD;
    #pragma unroll
    for (int ti = 0; ti < 4; ti++) {
        const float invd = 1.f / den[t0 + ti];
        float4 w = {o[ti][0] * invd, o[ti][1] * invd, o[ti][2] * invd, o[ti][3] * invd};
        *(float4*)&yb[(size_t)(t0 + ti) * CDIM + j0] = w;
    }
}

// ---------------------------------------------------------------------------
extern "C" void kernel_launch(void* const* d_in, const int* in_sizes, int n_in,
                              void* d_out, int out_size)
{
    const float* x  = (const float*)d_in[0];
    const float* Wa = (const float*)d_in[1];
    const float* ba = (const float*)d_in[2];
    const float* Wp = (const float*)d_in[3];
    const float* bp = (const float*)d_in[4];
    float* out = (float*)d_out;

    float *qkv, *y;
    __nv_bfloat16 *xhi, *xlo, *yhi, *ylo, *wahi, *walo, *wphi, *wplo;
    cudaGetSymbolAddress((void**)&qkv, g_qkv);
    cudaGetSymbolAddress((void**)&y, g_y);
    cudaGetSymbolAddress((void**)&xhi, g_xhi);
    cudaGetSymbolAddress((void**)&xlo, g_xlo);
    cudaGetSymbolAddress((void**)&yhi, g_yhi);
    cudaGetSymbolAddress((void**)&ylo, g_ylo);
    cudaGetSymbolAddress((void**)&wahi, g_wahi);
    cudaGetSymbolAddress((void**)&walo, g_walo);
    cudaGetSymbolAddress((void**)&wphi, g_wphi);
    cudaGetSymbolAddress((void**)&wplo, g_wplo);

    cudaFuncSetAttribute(gemm_bf16x3, cudaFuncAttributeMaxDynamicSharedMemorySize, GEMM_SMEM);
    const size_t smem4 = (size_t)(5 * 64 * 68 + 128) * sizeof(float);
    cudaFuncSetAttribute(attn_out, cudaFuncAttributeMaxDynamicSharedMemorySize, (int)smem4);

    // 0) split inputs to bf16 hi/lo (weights also transposed to [N,K])
    {
        const int nx = MROWS * CDIM;
        split_rm<<<nx / 1024, 256>>>(x, xhi, xlo, nx);
        dim3 ga(3 * CDIM / 32, CDIM / 32);
        split_tr<<<ga, 256>>>(Wa, wahi, walo, CDIM, 3 * CDIM);
        dim3 gp(CDIM / 32, CDIM / 32);
        split_tr<<<gp, 256>>>(Wp, wphi, wplo, CDIM, CDIM);
    }
    // 1) qkv = x @ W_attn + b_attn  (HMMA, 3-way bf16 split)
    {
        dim3 grid(3 * CDIM / 128, MROWS / 128);
        gemm_bf16x3<<<grid, 512, GEMM_SMEM>>>(xhi, xlo, wahi, walo, ba, qkv, 3 * CDIM, CDIM);
    }
    // 2-4) chunked linear attention
    chunk_stats<<<BH * NC, 256>>>();
    chunk_scan<<<BH, 256>>>();
    attn_out<<<BH * NC, 256, smem4>>>();
    // 5) split y, then out = y @ W_proj + b_proj
    {
        const int ny = MROWS * CDIM;
        split_rm<<<ny / 1024, 256>>>(y, yhi, ylo, ny);
        dim3 grid(CDIM / 128, MROWS / 128);
        gemm_bf16x3<<<grid, 512, GEMM_SMEM>>>(yhi, ylo, wphi, wplo, bp, out, CDIM, CDIM);
    }
}